// round 3
// baseline (speedup 1.0000x reference)
#include <cuda_runtime.h>

// AudioDeviceModel_89008902242543
//
// Reference reduces to (see analysis):
//   s[b]      = dot(x[b, 0:L], w1[0, 0:L, 0]) + b1 + b2 + b3 + b4 + b5
//   out[b, d] = s[b] * wd[0, d] + bd[d]          (B=8192, L=16384, D=128)
//
// The dilated convs c2..c5 operate on a spatial axis of length 1 with taps at
// +-d/2, entirely in SAME padding -> they contribute only their biases.
//
// HBM-read-bound: 512 MB of x. One CTA per 8 rows amortizes the w1 stream 8x.

#define B_ROWS 8192
#define L_COLS 16384
#define L4     (L_COLS / 4)   // 4096 float4 per row
#define RPB    8              // rows per block
#define NT     256            // threads per block
#define NWARPS (NT / 32)

__global__ __launch_bounds__(NT)
void audio_model_kernel(const float* __restrict__ x,
                        const float* __restrict__ w1,
                        const float* __restrict__ b1,
                        const float* __restrict__ b2,
                        const float* __restrict__ b3,
                        const float* __restrict__ b4,
                        const float* __restrict__ b5,
                        const float* __restrict__ wd,
                        const float* __restrict__ bd,
                        float* __restrict__ out)
{
    const int b0  = blockIdx.x * RPB;
    const int tid = threadIdx.x;

    const float4* __restrict__ wv = reinterpret_cast<const float4*>(w1);
    const float4* __restrict__ xv =
        reinterpret_cast<const float4*>(x) + (size_t)b0 * L4;

    float acc[RPB];
#pragma unroll
    for (int r = 0; r < RPB; r++) acc[r] = 0.0f;

    // Main reduction: each iteration = 1 w-float4 (L2-resident) + 8 x-float4
    // (HBM streams). 9 independent loads in flight per iter -> good MLP.
    for (int i = tid; i < L4; i += NT) {
        float4 w = wv[i];
#pragma unroll
        for (int r = 0; r < RPB; r++) {
            float4 xx = xv[(size_t)r * L4 + i];
            acc[r] = fmaf(xx.x, w.x,
                     fmaf(xx.y, w.y,
                     fmaf(xx.z, w.z,
                     fmaf(xx.w, w.w, acc[r]))));
        }
    }

    // Intra-warp tree reduction for each row accumulator.
#pragma unroll
    for (int r = 0; r < RPB; r++) {
#pragma unroll
        for (int off = 16; off > 0; off >>= 1)
            acc[r] += __shfl_xor_sync(0xffffffffu, acc[r], off);
    }

    __shared__ float part[NWARPS][RPB];
    __shared__ float srow[RPB];

    const int wid = tid >> 5;
    const int lid = tid & 31;
    if (lid == 0) {
#pragma unroll
        for (int r = 0; r < RPB; r++) part[wid][r] = acc[r];
    }
    __syncthreads();

    if (tid < RPB) {
        float s = 0.0f;
#pragma unroll
        for (int w = 0; w < NWARPS; w++) s += part[w][tid];
        s += b1[0] + b2[0] + b3[0] + b4[0] + b5[0];
        srow[tid] = s;
    }
    __syncthreads();

    // Epilogue: 8 rows x 128 outputs = 1024 stores, 4 per thread.
#pragma unroll
    for (int j = tid; j < RPB * 128; j += NT) {
        const int r = j >> 7;
        const int d = j & 127;
        out[(size_t)(b0 + r) * 128 + d] = fmaf(srow[r], wd[d], bd[d]);
    }
}

extern "C" void kernel_launch(void* const* d_in, const int* in_sizes, int n_in,
                              void* d_out, int out_size)
{
    // metadata order: x, w1, b1, w2, b2, w3, b3, w4, b4, w5, b5, wd, bd
    const float* x  = (const float*)d_in[0];
    const float* w1 = (const float*)d_in[1];
    const float* b1 = (const float*)d_in[2];
    const float* b2 = (const float*)d_in[4];
    const float* b3 = (const float*)d_in[6];
    const float* b4 = (const float*)d_in[8];
    const float* b5 = (const float*)d_in[10];
    const float* wd = (const float*)d_in[11];
    const float* bd = (const float*)d_in[12];
    float* out = (float*)d_out;

    dim3 grid(B_ROWS / RPB);   // 1024 CTAs
    audio_model_kernel<<<grid, NT>>>(x, w1, b1, b2, b3, b4, b5, wd, bd, out);
}

// round 4
// speedup vs baseline: 1.2615x; 1.2615x over previous
#include <cuda_runtime.h>

// AudioDeviceModel_89008902242543  — R3
//
// s[b]      = dot(x[b,:], w1[0,:,0]) + b1+b2+b3+b4+b5
// out[b,d]  = s[b]*wd[d] + bd[d]            (B=8192, L=16384, D=128)
//
// HBM-read-bound (512 MB of x). R2 hit 64.9% DRAM at regs=38 (loads
// interleaved with FMAs -> low MLP). R3 forces front-batched loads:
// separate load loop into a register block, 64-reg budget via
// __launch_bounds__(256, 4) so ptxas keeps all 9 LDG.128 in flight.

#define B_ROWS 8192
#define L_COLS 16384
#define L4     (L_COLS / 4)   // 4096 float4 per row
#define RPB    8              // rows per block
#define NT     256            // threads per block
#define NWARPS (NT / 32)
#define ITERS  (L4 / NT)      // 16

__global__ __launch_bounds__(NT, 4)
void audio_model_kernel(const float* __restrict__ x,
                        const float* __restrict__ w1,
                        const float* __restrict__ b1,
                        const float* __restrict__ b2,
                        const float* __restrict__ b3,
                        const float* __restrict__ b4,
                        const float* __restrict__ b5,
                        const float* __restrict__ wd,
                        const float* __restrict__ bd,
                        float* __restrict__ out)
{
    const int b0  = blockIdx.x * RPB;
    const int tid = threadIdx.x;

    const float4* __restrict__ wv = reinterpret_cast<const float4*>(w1);
    const float4* __restrict__ xv =
        reinterpret_cast<const float4*>(x) + (size_t)b0 * L4;

    float acc[RPB];
#pragma unroll
    for (int r = 0; r < RPB; r++) acc[r] = 0.0f;

    int i = tid;
#pragma unroll 1
    for (int it = 0; it < ITERS; ++it, i += NT) {
        // Front-batched loads: 1 w (L2-hit) + 8 x (HBM streams), all issued
        // before any FMA consumes them -> 9 LDG.128 outstanding per warp.
        float4 w = wv[i];
        float4 xx[RPB];
#pragma unroll
        for (int r = 0; r < RPB; r++)
            xx[r] = xv[(size_t)r * L4 + i];

#pragma unroll
        for (int r = 0; r < RPB; r++)
            acc[r] = fmaf(xx[r].x, w.x,
                     fmaf(xx[r].y, w.y,
                     fmaf(xx[r].z, w.z,
                     fmaf(xx[r].w, w.w, acc[r]))));
    }

    // Intra-warp tree reduction for each row accumulator.
#pragma unroll
    for (int r = 0; r < RPB; r++) {
#pragma unroll
        for (int off = 16; off > 0; off >>= 1)
            acc[r] += __shfl_xor_sync(0xffffffffu, acc[r], off);
    }

    __shared__ float part[NWARPS][RPB];
    __shared__ float srow[RPB];

    const int wid = tid >> 5;
    const int lid = tid & 31;
    if (lid == 0) {
#pragma unroll
        for (int r = 0; r < RPB; r++) part[wid][r] = acc[r];
    }
    __syncthreads();

    if (tid < RPB) {
        float s = 0.0f;
#pragma unroll
        for (int w = 0; w < NWARPS; w++) s += part[w][tid];
        s += b1[0] + b2[0] + b3[0] + b4[0] + b5[0];
        srow[tid] = s;
    }
    __syncthreads();

    // Epilogue: 8 rows x 128 outputs, coalesced.
#pragma unroll
    for (int j = tid; j < RPB * 128; j += NT) {
        const int r = j >> 7;
        const int d = j & 127;
        out[(size_t)(b0 + r) * 128 + d] = fmaf(srow[r], wd[d], bd[d]);
    }
}

extern "C" void kernel_launch(void* const* d_in, const int* in_sizes, int n_in,
                              void* d_out, int out_size)
{
    // metadata order: x, w1, b1, w2, b2, w3, b3, w4, b4, w5, b5, wd, bd
    const float* x  = (const float*)d_in[0];
    const float* w1 = (const float*)d_in[1];
    const float* b1 = (const float*)d_in[2];
    const float* b2 = (const float*)d_in[4];
    const float* b3 = (const float*)d_in[6];
    const float* b4 = (const float*)d_in[8];
    const float* b5 = (const float*)d_in[10];
    const float* wd = (const float*)d_in[11];
    const float* bd = (const float*)d_in[12];
    float* out = (float*)d_out;

    dim3 grid(B_ROWS / RPB);   // 1024 CTAs
    audio_model_kernel<<<grid, NT>>>(x, w1, b1, b2, b3, b4, b5, wd, bd, out);
}

// round 5
// speedup vs baseline: 1.2667x; 1.0042x over previous
#include <cuda_runtime.h>

// AudioDeviceModel_89008902242543  — R4
//
// s[b]      = dot(x[b,:], w1[0,:,0]) + b1+b2+b3+b4+b5
// out[b,d]  = s[b]*wd[d] + bd[d]            (B=8192, L=16384, D=128)
//
// HBM-read-bound (512 MB of x). R3: front-batched loads -> 83% DRAM.
// R4: ping-pong double buffer so next block's 8 LDG.128 are in flight
// during current block's FMAs (no scoreboard drain bubble), __ldcs
// streaming hints, occ=3 (85-reg budget for the two register blocks).

#define B_ROWS 8192
#define L_COLS 16384
#define L4     (L_COLS / 4)   // 4096 float4 per row
#define RPB    8              // rows per block
#define NT     256            // threads per block
#define NWARPS (NT / 32)
#define ITERS  (L4 / NT)      // 16 (even)

__device__ __forceinline__ float dot4_acc(float4 xx, float4 w, float a) {
    return fmaf(xx.x, w.x, fmaf(xx.y, w.y, fmaf(xx.z, w.z, fmaf(xx.w, w.w, a))));
}

__global__ __launch_bounds__(NT, 3)
void audio_model_kernel(const float* __restrict__ x,
                        const float* __restrict__ w1,
                        const float* __restrict__ b1,
                        const float* __restrict__ b2,
                        const float* __restrict__ b3,
                        const float* __restrict__ b4,
                        const float* __restrict__ b5,
                        const float* __restrict__ wd,
                        const float* __restrict__ bd,
                        float* __restrict__ out)
{
    const int b0  = blockIdx.x * RPB;
    const int tid = threadIdx.x;

    const float4* __restrict__ wv = reinterpret_cast<const float4*>(w1);
    const float4* __restrict__ xv =
        reinterpret_cast<const float4*>(x) + (size_t)b0 * L4;

    float acc[RPB];
#pragma unroll
    for (int r = 0; r < RPB; r++) acc[r] = 0.0f;

    float4 xa[RPB], xb[RPB];

    int i = tid;

    // Prologue: block A in flight.
#pragma unroll
    for (int r = 0; r < RPB; r++)
        xa[r] = __ldcs(&xv[(size_t)r * L4 + i]);

#pragma unroll 1
    for (int it = 0; it < ITERS - 2; it += 2) {
        const int ib = i + NT;
        // Prefetch block B while A's loads are landing / FMAs run.
#pragma unroll
        for (int r = 0; r < RPB; r++)
            xb[r] = __ldcs(&xv[(size_t)r * L4 + ib]);

        // Consume A (w is an L2 hit; loaded just-in-time to save regs).
        {
            float4 w = wv[i];
#pragma unroll
            for (int r = 0; r < RPB; r++)
                acc[r] = dot4_acc(xa[r], w, acc[r]);
        }

        const int ia = i + 2 * NT;
        // Prefetch next block A while B's loads land / FMAs run.
#pragma unroll
        for (int r = 0; r < RPB; r++)
            xa[r] = __ldcs(&xv[(size_t)r * L4 + ia]);

        // Consume B.
        {
            float4 w = wv[ib];
#pragma unroll
            for (int r = 0; r < RPB; r++)
                acc[r] = dot4_acc(xb[r], w, acc[r]);
        }

        i += 2 * NT;
    }

    // Peeled final pair (no further prefetch — avoids OOB / redundant loads).
    {
        const int ib = i + NT;
#pragma unroll
        for (int r = 0; r < RPB; r++)
            xb[r] = __ldcs(&xv[(size_t)r * L4 + ib]);
        {
            float4 w = wv[i];
#pragma unroll
            for (int r = 0; r < RPB; r++)
                acc[r] = dot4_acc(xa[r], w, acc[r]);
        }
        {
            float4 w = wv[ib];
#pragma unroll
            for (int r = 0; r < RPB; r++)
                acc[r] = dot4_acc(xb[r], w, acc[r]);
        }
    }

    // Intra-warp tree reduction for each row accumulator.
#pragma unroll
    for (int r = 0; r < RPB; r++) {
#pragma unroll
        for (int off = 16; off > 0; off >>= 1)
            acc[r] += __shfl_xor_sync(0xffffffffu, acc[r], off);
    }

    __shared__ float part[NWARPS][RPB];
    __shared__ float srow[RPB];

    const int wid = tid >> 5;
    const int lid = tid & 31;
    if (lid == 0) {
#pragma unroll
        for (int r = 0; r < RPB; r++) part[wid][r] = acc[r];
    }
    __syncthreads();

    if (tid < RPB) {
        float s = 0.0f;
#pragma unroll
        for (int w = 0; w < NWARPS; w++) s += part[w][tid];
        s += b1[0] + b2[0] + b3[0] + b4[0] + b5[0];
        srow[tid] = s;
    }
    __syncthreads();

    // Epilogue: 8 rows x 128 outputs, coalesced.
#pragma unroll
    for (int j = tid; j < RPB * 128; j += NT) {
        const int r = j >> 7;
        const int d = j & 127;
        out[(size_t)(b0 + r) * 128 + d] = fmaf(srow[r], wd[d], bd[d]);
    }
}

extern "C" void kernel_launch(void* const* d_in, const int* in_sizes, int n_in,
                              void* d_out, int out_size)
{
    // metadata order: x, w1, b1, w2, b2, w3, b3, w4, b4, w5, b5, wd, bd
    const float* x  = (const float*)d_in[0];
    const float* w1 = (const float*)d_in[1];
    const float* b1 = (const float*)d_in[2];
    const float* b2 = (const float*)d_in[4];
    const float* b3 = (const float*)d_in[6];
    const float* b4 = (const float*)d_in[8];
    const float* b5 = (const float*)d_in[10];
    const float* wd = (const float*)d_in[11];
    const float* bd = (const float*)d_in[12];
    float* out = (float*)d_out;

    dim3 grid(B_ROWS / RPB);   // 1024 CTAs
    audio_model_kernel<<<grid, NT>>>(x, w1, b1, b2, b3, b4, b5, wd, bd, out);
}

// round 6
// speedup vs baseline: 1.2999x; 1.0262x over previous
#include <cuda_runtime.h>

// AudioDeviceModel_89008902242543  — R5
//
// s[b]      = dot(x[b,:], w1[0,:,0]) + b1+b2+b3+b4+b5
// out[b,d]  = s[b]*wd[d] + bd[d]            (B=8192, L=16384, D=128)
//
// HBM-read-bound (512 MB of x), plateaued at ~6.55 TB/s (82-83% DRAM) in
// R3/R4. R4's double-buffer was neutral (occupancy loss offset pipelining)
// -> reverted. R5 tests the scheduling-tail hypothesis: RPB 8->4 doubles
// grid to 2048 (3.5 waves @ occ4, halved tail fraction, shorter CTAs),
// with a x2-unrolled front-batch (8 x-LDG.128 + 2 w per unit) to keep MLP.

#define B_ROWS 8192
#define L_COLS 16384
#define L4     (L_COLS / 4)   // 4096 float4 per row
#define RPB    4              // rows per block
#define NT     256            // threads per block
#define NWARPS (NT / 32)
#define ITERS  (L4 / NT)      // 16 (even) -> 8 unrolled-x2 steps

__device__ __forceinline__ float dot4_acc(float4 xx, float4 w, float a) {
    return fmaf(xx.x, w.x, fmaf(xx.y, w.y, fmaf(xx.z, w.z, fmaf(xx.w, w.w, a))));
}

__global__ __launch_bounds__(NT, 4)
void audio_model_kernel(const float* __restrict__ x,
                        const float* __restrict__ w1,
                        const float* __restrict__ b1,
                        const float* __restrict__ b2,
                        const float* __restrict__ b3,
                        const float* __restrict__ b4,
                        const float* __restrict__ b5,
                        const float* __restrict__ wd,
                        const float* __restrict__ bd,
                        float* __restrict__ out)
{
    const int b0  = blockIdx.x * RPB;
    const int tid = threadIdx.x;

    const float4* __restrict__ wv = reinterpret_cast<const float4*>(w1);
    const float4* __restrict__ xv =
        reinterpret_cast<const float4*>(x) + (size_t)b0 * L4;

    float acc[RPB];
#pragma unroll
    for (int r = 0; r < RPB; r++) acc[r] = 0.0f;

    int i = tid;
#pragma unroll 1
    for (int it = 0; it < ITERS; it += 2, i += 2 * NT) {
        const int ib = i + NT;

        // Front-batched: 8 x-LDG.128 (HBM streams) + 2 w loads (L2 hits),
        // all issued before any FMA consumes them.
        float4 wA = wv[i];
        float4 wB = wv[ib];
        float4 xa[RPB], xb[RPB];
#pragma unroll
        for (int r = 0; r < RPB; r++) xa[r] = __ldcs(&xv[(size_t)r * L4 + i]);
#pragma unroll
        for (int r = 0; r < RPB; r++) xb[r] = __ldcs(&xv[(size_t)r * L4 + ib]);

#pragma unroll
        for (int r = 0; r < RPB; r++) acc[r] = dot4_acc(xa[r], wA, acc[r]);
#pragma unroll
        for (int r = 0; r < RPB; r++) acc[r] = dot4_acc(xb[r], wB, acc[r]);
    }

    // Intra-warp tree reduction for each row accumulator.
#pragma unroll
    for (int r = 0; r < RPB; r++) {
#pragma unroll
        for (int off = 16; off > 0; off >>= 1)
            acc[r] += __shfl_xor_sync(0xffffffffu, acc[r], off);
    }

    __shared__ float part[NWARPS][RPB];
    __shared__ float srow[RPB];

    const int wid = tid >> 5;
    const int lid = tid & 31;
    if (lid == 0) {
#pragma unroll
        for (int r = 0; r < RPB; r++) part[wid][r] = acc[r];
    }
    __syncthreads();

    if (tid < RPB) {
        float s = 0.0f;
#pragma unroll
        for (int w = 0; w < NWARPS; w++) s += part[w][tid];
        s += b1[0] + b2[0] + b3[0] + b4[0] + b5[0];
        srow[tid] = s;
    }
    __syncthreads();

    // Epilogue: 4 rows x 128 outputs, coalesced (2 stores per thread).
#pragma unroll
    for (int j = tid; j < RPB * 128; j += NT) {
        const int r = j >> 7;
        const int d = j & 127;
        out[(size_t)(b0 + r) * 128 + d] = fmaf(srow[r], wd[d], bd[d]);
    }
}

extern "C" void kernel_launch(void* const* d_in, const int* in_sizes, int n_in,
                              void* d_out, int out_size)
{
    // metadata order: x, w1, b1, w2, b2, w3, b3, w4, b4, w5, b5, wd, bd
    const float* x  = (const float*)d_in[0];
    const float* w1 = (const float*)d_in[1];
    const float* b1 = (const float*)d_in[2];
    const float* b2 = (const float*)d_in[4];
    const float* b3 = (const float*)d_in[6];
    const float* b4 = (const float*)d_in[8];
    const float* b5 = (const float*)d_in[10];
    const float* wd = (const float*)d_in[11];
    const float* bd = (const float*)d_in[12];
    float* out = (float*)d_out;

    dim3 grid(B_ROWS / RPB);   // 2048 CTAs
    audio_model_kernel<<<grid, NT>>>(x, w1, b1, b2, b3, b4, b5, wd, bd, out);
}

// round 7
// speedup vs baseline: 1.3163x; 1.0127x over previous
#include <cuda_runtime.h>

// AudioDeviceModel_89008902242543  — R6
//
// s[b]      = dot(x[b,:], w1[0,:,0]) + b1+b2+b3+b4+b5
// out[b,d]  = s[b]*wd[d] + bd[d]            (B=8192, L=16384, D=128)
//
// HBM-read-bound (512 MB of x). R5 confirmed the scheduling-tail theory
// (2x waves -> -2.1us, 84.1% DRAM). R6 pushes the same axis: RPB 2,
// grid 4096, ~6.9 waves @ occ 4. MLP kept at 8 x-LDG.128 per unit via
// x4 column unroll; w loaded JIT (L2 hits) to stay under 64 regs.

#define B_ROWS 8192
#define L_COLS 16384
#define L4     (L_COLS / 4)   // 4096 float4 per row
#define RPB    2              // rows per block
#define NT     256            // threads per block
#define NWARPS (NT / 32)
#define UNR    4              // column steps per batch
#define ITERS  (L4 / NT)      // 16 -> 4 batches of UNR

__device__ __forceinline__ float dot4_acc(float4 xx, float4 w, float a) {
    return fmaf(xx.x, w.x, fmaf(xx.y, w.y, fmaf(xx.z, w.z, fmaf(xx.w, w.w, a))));
}

__global__ __launch_bounds__(NT, 4)
void audio_model_kernel(const float* __restrict__ x,
                        const float* __restrict__ w1,
                        const float* __restrict__ b1,
                        const float* __restrict__ b2,
                        const float* __restrict__ b3,
                        const float* __restrict__ b4,
                        const float* __restrict__ b5,
                        const float* __restrict__ wd,
                        const float* __restrict__ bd,
                        float* __restrict__ out)
{
    const int b0  = blockIdx.x * RPB;
    const int tid = threadIdx.x;

    const float4* __restrict__ wv = reinterpret_cast<const float4*>(w1);
    const float4* __restrict__ xv =
        reinterpret_cast<const float4*>(x) + (size_t)b0 * L4;

    float acc[RPB];
#pragma unroll
    for (int r = 0; r < RPB; r++) acc[r] = 0.0f;

    int i = tid;
#pragma unroll 1
    for (int it = 0; it < ITERS; it += UNR, i += UNR * NT) {
        // Front-batch the 8 HBM loads (2 rows x 4 column steps).
        float4 xx[RPB][UNR];
#pragma unroll
        for (int u = 0; u < UNR; u++)
#pragma unroll
            for (int r = 0; r < RPB; r++)
                xx[r][u] = __ldcs(&xv[(size_t)r * L4 + i + u * NT]);

        // w loads are L2 hits; JIT to save registers.
#pragma unroll
        for (int u = 0; u < UNR; u++) {
            float4 w = wv[i + u * NT];
#pragma unroll
            for (int r = 0; r < RPB; r++)
                acc[r] = dot4_acc(xx[r][u], w, acc[r]);
        }
    }

    // Intra-warp tree reduction for each row accumulator.
#pragma unroll
    for (int r = 0; r < RPB; r++) {
#pragma unroll
        for (int off = 16; off > 0; off >>= 1)
            acc[r] += __shfl_xor_sync(0xffffffffu, acc[r], off);
    }

    __shared__ float part[NWARPS][RPB];
    __shared__ float srow[RPB];

    const int wid = tid >> 5;
    const int lid = tid & 31;
    if (lid == 0) {
#pragma unroll
        for (int r = 0; r < RPB; r++) part[wid][r] = acc[r];
    }
    __syncthreads();

    if (tid < RPB) {
        float s = 0.0f;
#pragma unroll
        for (int w = 0; w < NWARPS; w++) s += part[w][tid];
        s += b1[0] + b2[0] + b3[0] + b4[0] + b5[0];
        srow[tid] = s;
    }
    __syncthreads();

    // Epilogue: 2 rows x 128 outputs, coalesced (1 store per thread).
#pragma unroll
    for (int j = tid; j < RPB * 128; j += NT) {
        const int r = j >> 7;
        const int d = j & 127;
        out[(size_t)(b0 + r) * 128 + d] = fmaf(srow[r], wd[d], bd[d]);
    }
}

extern "C" void kernel_launch(void* const* d_in, const int* in_sizes, int n_in,
                              void* d_out, int out_size)
{
    // metadata order: x, w1, b1, w2, b2, w3, b3, w4, b4, w5, b5, wd, bd
    const float* x  = (const float*)d_in[0];
    const float* w1 = (const float*)d_in[1];
    const float* b1 = (const float*)d_in[2];
    const float* b2 = (const float*)d_in[4];
    const float* b3 = (const float*)d_in[6];
    const float* b4 = (const float*)d_in[8];
    const float* b5 = (const float*)d_in[10];
    const float* wd = (const float*)d_in[11];
    const float* bd = (const float*)d_in[12];
    float* out = (float*)d_out;

    dim3 grid(B_ROWS / RPB);   // 4096 CTAs
    audio_model_kernel<<<grid, NT>>>(x, w1, b1, b2, b3, b4, b5, wd, bd, out);
}

// round 8
// speedup vs baseline: 1.3258x; 1.0072x over previous
#include <cuda_runtime.h>

// AudioDeviceModel_89008902242543  — R7
//
// s[b]      = dot(x[b,:], w1[0,:,0]) + b1+b2+b3+b4+b5
// out[b,d]  = s[b]*wd[d] + bd[d]            (B=8192, L=16384, D=128)
//
// HBM-read-bound (512 MB of x). Wave-tail axis validated twice
// (R5: 2x waves -2.1us, R6: 2x waves -1.0us, 86.6% DRAM). R7: final
// step, RPB=1, grid 8192, ~13.8 waves @ occ 4. MLP kept at 8 LDG.128
// per unit via x8 column unroll; w loaded JIT (L2-resident, 64 KB).

#define B_ROWS 8192
#define L_COLS 16384
#define L4     (L_COLS / 4)   // 4096 float4 per row
#define NT     256            // threads per block
#define NWARPS (NT / 32)
#define UNR    8              // column steps per batch
#define ITERS  (L4 / NT)      // 16 -> 2 batches of UNR

__device__ __forceinline__ float dot4_acc(float4 xx, float4 w, float a) {
    return fmaf(xx.x, w.x, fmaf(xx.y, w.y, fmaf(xx.z, w.z, fmaf(xx.w, w.w, a))));
}

__global__ __launch_bounds__(NT, 4)
void audio_model_kernel(const float* __restrict__ x,
                        const float* __restrict__ w1,
                        const float* __restrict__ b1,
                        const float* __restrict__ b2,
                        const float* __restrict__ b3,
                        const float* __restrict__ b4,
                        const float* __restrict__ b5,
                        const float* __restrict__ wd,
                        const float* __restrict__ bd,
                        float* __restrict__ out)
{
    const int row = blockIdx.x;
    const int tid = threadIdx.x;

    const float4* __restrict__ wv = reinterpret_cast<const float4*>(w1);
    const float4* __restrict__ xv =
        reinterpret_cast<const float4*>(x) + (size_t)row * L4;

    float acc = 0.0f;

    int i = tid;
#pragma unroll 1
    for (int it = 0; it < ITERS; it += UNR, i += UNR * NT) {
        // Front-batch 8 HBM LDG.128 for this row before any consumption.
        float4 xx[UNR];
#pragma unroll
        for (int u = 0; u < UNR; u++)
            xx[u] = __ldcs(&xv[i + u * NT]);

        // w loads are L2 hits; JIT to save registers.
#pragma unroll
        for (int u = 0; u < UNR; u++) {
            float4 w = wv[i + u * NT];
            acc = dot4_acc(xx[u], w, acc);
        }
    }

    // Intra-warp tree reduction.
#pragma unroll
    for (int off = 16; off > 0; off >>= 1)
        acc += __shfl_xor_sync(0xffffffffu, acc, off);

    __shared__ float part[NWARPS];
    __shared__ float srow;

    const int wid = tid >> 5;
    const int lid = tid & 31;
    if (lid == 0) part[wid] = acc;
    __syncthreads();

    if (tid == 0) {
        float s = 0.0f;
#pragma unroll
        for (int w = 0; w < NWARPS; w++) s += part[w];
        s += b1[0] + b2[0] + b3[0] + b4[0] + b5[0];
        srow = s;
    }
    __syncthreads();

    // Epilogue: 128 outputs for this row, coalesced.
    if (tid < 128)
        out[(size_t)row * 128 + tid] = fmaf(srow, wd[tid], bd[tid]);
}

extern "C" void kernel_launch(void* const* d_in, const int* in_sizes, int n_in,
                              void* d_out, int out_size)
{
    // metadata order: x, w1, b1, w2, b2, w3, b3, w4, b4, w5, b5, wd, bd
    const float* x  = (const float*)d_in[0];
    const float* w1 = (const float*)d_in[1];
    const float* b1 = (const float*)d_in[2];
    const float* b2 = (const float*)d_in[4];
    const float* b3 = (const float*)d_in[6];
    const float* b4 = (const float*)d_in[8];
    const float* b5 = (const float*)d_in[10];
    const float* wd = (const float*)d_in[11];
    const float* bd = (const float*)d_in[12];
    float* out = (float*)d_out;

    dim3 grid(B_ROWS);   // 8192 CTAs, one row each
    audio_model_kernel<<<grid, NT>>>(x, w1, b1, b2, b3, b4, b5, wd, bd, out);
}